// round 14
// baseline (speedup 1.0000x reference)
#include <cuda_runtime.h>
#include <stdint.h>

// Fixed problem shapes
#define NB 32
#define NS 32
#define NW 30
#define NE 300
#define NEV 75                   // float4 per embedding row (300 floats)
#define NSENT (NB * NS)          // 1024
#define EMB_ELEMS (NSENT * NW * NE)          // 9,216,000
#define OFF_SHARE  EMB_ELEMS
#define OFF_MASK   (2 * EMB_ELEMS)           // 18,432,000
#define OFF_WMASK  (OFF_MASK + NSENT * NW)
#define OFF_SMASK  (OFF_WMASK + NSENT * NW)

#define SENT_VEC  (NW * NEV)     // 2250 float4 per sentence
#define BLOCK     512
#define GRID      512            // persistent single wave; 2 sentences per CTA
#define NITER     5              // 4 full + 1 tail (202 lanes)

__global__ __launch_bounds__(BLOCK, 4) void embed_fused_kernel(
    const int* __restrict__ input_var,        // [1024*30] int32 tokens
    const float* __restrict__ W_emb,          // [50000*300]
    float* __restrict__ out)
{
    const int tid  = threadIdx.x;
    const int lane = tid & 31;
    const float4* __restrict__ emb4 = (const float4*)W_emb;

    #pragma unroll
    for (int pass = 0; pass < 2; pass++) {
        const int sent = blockIdx.x + pass * GRID;   // 0..511, then 512..1023

        // Every warp loads tokens redundantly (lane l holds tok[l]); no SMEM, no syncs.
        const int t = (lane < NW) ? __ldg(&input_var[sent * NW + lane]) : 1;
        const unsigned nz = __ballot_sync(0xFFFFFFFFu, t != 0);
        const unsigned firstzero = ~nz;                  // lowest set bit = first zero
        const unsigned kmask = (firstzero - 1u) & ~firstzero & 0x3FFFFFFFu;

        // Masks: warp 0 only
        if (tid < NW) {
            out[OFF_MASK  + sent * NW + tid] = (kmask >> tid & 1u) ? 1.0f : 0.0f;
            out[OFF_WMASK + sent * NW + tid] = (t != 0) ? 1.0f : 0.0f;
        }
        if (tid == 0) {
            out[OFF_SMASK + sent] = ((nz & 0x3FFFFFFFu) != 0u) ? 1.0f : 0.0f;
        }

        float4* __restrict__ out_e = (float4*)out + (size_t)sent * SENT_VEC;
        float4* __restrict__ out_s = (float4*)(out + OFF_SHARE) + (size_t)sent * SENT_VEC;

        // Phase 1: batched gathers; token for row w fetched via shfl from lane w.
        // i=0..3 provably in-bounds (tid+1536 <= 2047 < 2250).
        float4 vals[NITER];
        #pragma unroll
        for (int i = 0; i < 4; i++) {
            const int v = tid + i * BLOCK;
            const int w = v / NEV;
            const int j = v - w * NEV;
            const int tok = __shfl_sync(0xFFFFFFFFu, t, w);
            vals[i] = __ldg(&emb4[(size_t)tok * NEV + j]);
        }
        // Tail: collective shfl OUTSIDE the divergent branch (all 32 lanes participate;
        // w clamped to a valid lane for OOB threads), only the load is predicated.
        {
            const int v = tid + 4 * BLOCK;
            const bool ok = (v < SENT_VEC);
            const int w = ok ? v / NEV : (NW - 1);
            const int j = v - w * NEV;
            const int tok = __shfl_sync(0xFFFFFFFFu, t, w);
            if (ok) vals[4] = __ldg(&emb4[(size_t)tok * NEV + j]);
        }

        // Phase 2: streaming stores; rare truncated token -> row 0 (predicated reload)
        #pragma unroll
        for (int i = 0; i < NITER; i++) {
            const int v = tid + i * BLOCK;
            if (i < 4 || v < SENT_VEC) {
                const int w = v / NEV;
                const int j = v - w * NEV;
                __stcs(&out_e[v], vals[i]);
                float4 x = vals[i];
                if (!(kmask >> w & 1u)) x = __ldg(&emb4[j]);   // row 0
                __stcs(&out_s[v], x);
            }
        }
    }
}

extern "C" void kernel_launch(void* const* d_in, const int* in_sizes, int n_in,
                              void* d_out, int out_size) {
    const int*   input_var = (const int*)d_in[0];
    const float* W_emb     = (const float*)d_in[1];
    float*       out       = (float*)d_out;

    embed_fused_kernel<<<GRID, BLOCK>>>(input_var, W_emb, out);
}

// round 15
// speedup vs baseline: 1.1366x; 1.1366x over previous
#include <cuda_runtime.h>
#include <stdint.h>

// Fixed problem shapes
#define NB 32
#define NS 32
#define NW 30
#define NE 300
#define NEV 75                   // float4 per embedding row (300 floats)
#define NSENT (NB * NS)          // 1024
#define EMB_ELEMS (NSENT * NW * NE)          // 9,216,000
#define OFF_SHARE  EMB_ELEMS
#define OFF_MASK   (2 * EMB_ELEMS)           // 18,432,000
#define OFF_WMASK  (OFF_MASK + NSENT * NW)
#define OFF_SMASK  (OFF_WMASK + NSENT * NW)

#define HALF_ROWS 15
#define HALF_VEC  (HALF_ROWS * NEV)          // 1125 float4 per half-sentence
#define BLOCK     256
#define NITER     5

__global__ __launch_bounds__(BLOCK, 8) void embed_fused_kernel(
    const int* __restrict__ input_var,        // [1024*30] int32 tokens
    const float* __restrict__ W_emb,          // [50000*300]
    float* __restrict__ out)
{
    const int sent = blockIdx.x >> 1;   // 0..1023
    const int half = blockIdx.x & 1;    // 0: rows 0-14, 1: rows 15-29
    const int tid  = threadIdx.x;

    __shared__ int s_tok[NW];
    __shared__ unsigned s_kmask;        // bit w set => token w kept (before first zero)

    // Warp 0: load tokens + compute all masks with one ballot
    if (tid < 32) {
        const int t = (tid < NW) ? input_var[sent * NW + tid] : 1;
        if (tid < NW) s_tok[tid] = t;
        const unsigned nz = __ballot_sync(0xFFFFFFFFu, t != 0);
        const unsigned firstzero = ~nz;                 // lowest set bit = first zero
        const unsigned keepmask  = (firstzero - 1u) & ~firstzero & 0x3FFFFFFFu;
        if (tid == 0) s_kmask = keepmask;
        if (half == 0 && tid < NW) {
            out[OFF_MASK  + sent * NW + tid] = (keepmask >> tid & 1u) ? 1.0f : 0.0f;
            out[OFF_WMASK + sent * NW + tid] = (t != 0) ? 1.0f : 0.0f;
        }
        if (half == 0 && tid == 0) {
            out[OFF_SMASK + sent] = ((nz & 0x3FFFFFFFu) != 0u) ? 1.0f : 0.0f;
        }
    }
    __syncthreads();

    const unsigned kmask = s_kmask;
    const float4* __restrict__ emb4 = (const float4*)W_emb;
    float4* __restrict__ out_e = (float4*)out
        + (size_t)sent * (NW * NEV) + half * HALF_VEC;
    float4* __restrict__ out_s = (float4*)(out + OFF_SHARE)
        + (size_t)sent * (NW * NEV) + half * HALF_VEC;
    const int rbase = half * HALF_ROWS;

    // Phase 1: batched gathers. i=0..3 provably in-bounds (tid+768 <= 1023 < 1125)
    float4 vals[NITER];
    #pragma unroll
    for (int i = 0; i < 4; i++) {
        const int v = tid + i * BLOCK;
        const int w = v / NEV;
        const int j = v - w * NEV;
        vals[i] = __ldg(&emb4[(size_t)s_tok[rbase + w] * NEV + j]);
    }
    const int v4 = tid + 4 * BLOCK;
    if (v4 < HALF_VEC) {
        const int w = v4 / NEV;
        const int j = v4 - w * NEV;
        vals[4] = __ldg(&emb4[(size_t)s_tok[rbase + w] * NEV + j]);
    }

    // Phase 2: block-uniform fast path — all rows of this half kept (99.9% of CTAs):
    // pure back-to-back streaming stores, no mask tests, no predicated reloads.
    if (((kmask >> rbase) & 0x7FFFu) == 0x7FFFu) {
        #pragma unroll
        for (int i = 0; i < NITER; i++) {
            const int v = tid + i * BLOCK;
            if (i < 4 || v < HALF_VEC) {
                __stcs(&out_e[v], vals[i]);
                __stcs(&out_s[v], vals[i]);
            }
        }
    } else {
        // Rare slow path: truncated token -> row 0
        #pragma unroll
        for (int i = 0; i < NITER; i++) {
            const int v = tid + i * BLOCK;
            if (i < 4 || v < HALF_VEC) {
                const int w = v / NEV;
                const int j = v - w * NEV;
                __stcs(&out_e[v], vals[i]);
                float4 x = vals[i];
                if (!(kmask >> (rbase + w) & 1u)) x = __ldg(&emb4[j]);   // row 0
                __stcs(&out_s[v], x);
            }
        }
    }
}

extern "C" void kernel_launch(void* const* d_in, const int* in_sizes, int n_in,
                              void* d_out, int out_size) {
    const int*   input_var = (const int*)d_in[0];
    const float* W_emb     = (const float*)d_in[1];
    float*       out       = (float*)d_out;

    embed_fused_kernel<<<2 * NSENT, BLOCK>>>(input_var, W_emb, out);
}